// round 1
// baseline (speedup 1.0000x reference)
#include <cuda_runtime.h>
#include <cuda_bf16.h>

// Retrace loss:
//  per row b (B=4096), stride S=1025, T=1024:
//    c[k]   = clip(tp[b,k]/bp[b,k], 1e-10, 1.0)
//    for j = 0..1022:
//       A[j] = r[b,j+1] + 0.99*eQ[b,j+2] - (0.99*c[j+2])*tQ[b,j+2]
//       B[j] = 0.99*c[j+2]
//    y[1023] = Q[b,1024]   (sentinel / init)
//    y[j] = A[j] + B[j]*y[j+1]              (backward recurrence)
//    loss += sum_{j=0..1022} (Q[b,j]-y[j])^2 + (Q[b,1023]-Q[b,1024])^2
//  output = loss / (4096*1024)
//
// Parallelized via suffix scan of affine maps (A,B):
//   (A1,B1) o (A2,B2) = (A1 + B1*A2, B1*B2)   (left map applied last)

#define S_STRIDE 1025
#define T_LEN    1024
#define NROWS    4096
#define GAMMA_F  0.99f
#define EPS_F    1e-10f
#define NTHREADS 256
#define ITEMS    4   // NTHREADS*ITEMS = 1024 slots; slot 1023 = identity pad

__device__ double g_acc;

struct Aff { float a, b; };

__device__ __forceinline__ Aff comp(Aff f, Aff g) {
    // f o g : apply g first, then f
    Aff r;
    r.a = fmaf(f.b, g.a, f.a);
    r.b = f.b * g.b;
    return r;
}

__global__ void zero_acc_kernel() { g_acc = 0.0; }

__global__ void __launch_bounds__(NTHREADS)
retrace_kernel(const float* __restrict__ Q,
               const float* __restrict__ eQ,
               const float* __restrict__ tQ,
               const float* __restrict__ r,
               const float* __restrict__ tp,
               const float* __restrict__ bp)
{
    const int row = blockIdx.x;
    const long base = (long)row * S_STRIDE;
    const int t = threadIdx.x;
    const unsigned lane = t & 31u;
    const unsigned w = t >> 5;
    const int j0 = t * ITEMS;

    // ---- build local affine maps + grab Q values (coalesced: 4 consecutive cols/thread)
    Aff loc[ITEMS];
    float qv[ITEMS];
#pragma unroll
    for (int k = 0; k < ITEMS; k++) {
        const int j = j0 + k;
        qv[k] = __ldg(&Q[base + j]);
        if (j < T_LEN - 1) {  // j <= 1022 : real map
            const float rv  = __ldg(&r[base + j + 1]);
            const float ev  = __ldg(&eQ[base + j + 2]);
            const float tqv = __ldg(&tQ[base + j + 2]);
            const float ptv = __ldg(&tp[base + j + 2]);
            const float pbv = __ldg(&bp[base + j + 2]);
            const float c   = fminf(fmaxf(ptv / pbv, EPS_F), 1.0f);
            const float B   = GAMMA_F * c;
            Aff f;
            f.b = B;
            f.a = fmaf(GAMMA_F, ev, rv) - B * tqv;
            loc[k] = f;
        } else {              // j == 1023 : identity pad
            loc[k].a = 0.0f; loc[k].b = 1.0f;
        }
    }

    // ---- per-thread local suffix composition: suf[k] = f_{j0+k} o ... o f_{j0+3}
    Aff suf[ITEMS];
    suf[ITEMS - 1] = loc[ITEMS - 1];
#pragma unroll
    for (int k = ITEMS - 2; k >= 0; k--) suf[k] = comp(loc[k], suf[k + 1]);

    // ---- warp-level inclusive suffix scan of thread aggregates
    Aff v = suf[0];
#pragma unroll
    for (int off = 1; off < 32; off <<= 1) {
        float oa = __shfl_down_sync(0xffffffffu, v.a, off);
        float ob = __shfl_down_sync(0xffffffffu, v.b, off);
        if (lane + off < 32) { Aff g; g.a = oa; g.b = ob; v = comp(v, g); }
    }
    // v = composition of aggregates of threads (lane..31) within this warp

    // in-warp EXCLUSIVE suffix (threads lane+1..31) — take before cross-warp combine
    float ea = __shfl_down_sync(0xffffffffu, v.a, 1);
    float eb = __shfl_down_sync(0xffffffffu, v.b, 1);
    Aff inwexcl;
    if (lane == 31) { inwexcl.a = 0.0f; inwexcl.b = 1.0f; }
    else            { inwexcl.a = ea;   inwexcl.b = eb;   }

    __shared__ float sA[8], sB[8];     // warp inclusive totals
    __shared__ float wA[8], wB[8];     // per-warp exclusive suffix (later warps)
    if (lane == 0) { sA[w] = v.a; sB[w] = v.b; }
    __syncthreads();
    if (t == 0) {
        Aff acc; acc.a = 0.0f; acc.b = 1.0f;
        for (int ww = 7; ww >= 0; ww--) {
            wA[ww] = acc.a; wB[ww] = acc.b;
            Aff tot; tot.a = sA[ww]; tot.b = sB[ww];
            acc = comp(tot, acc);
        }
    }
    __syncthreads();

    // exclusive suffix for this thread = (threads after it in warp) o (warps after it)
    Aff wex; wex.a = wA[w]; wex.b = wB[w];
    const Aff S = comp(inwexcl, wex);

    // ---- apply composed maps to init and accumulate squared error
    const float init = __ldg(&Q[base + T_LEN]);  // Q[b,1024]
    double lsum = 0.0;
#pragma unroll
    for (int k = 0; k < ITEMS; k++) {
        const int j = j0 + k;
        const Aff m = comp(suf[k], S);          // f_j o ... o f_1022 (o identity)
        const float y = fmaf(m.b, init, m.a);   // y_j ; for j==1023 equals init
        const float d = qv[k] - y;
        lsum += (double)d * (double)d;
    }

    // ---- block reduction (double) + one atomic per block
#pragma unroll
    for (int off = 16; off > 0; off >>= 1)
        lsum += __shfl_down_sync(0xffffffffu, lsum, off);
    __shared__ double ssum[8];
    if (lane == 0) ssum[w] = lsum;
    __syncthreads();
    if (w == 0) {
        double x = (lane < 8) ? ssum[lane] : 0.0;
#pragma unroll
        for (int off = 4; off > 0; off >>= 1)
            x += __shfl_down_sync(0xffffffffu, x, off);
        if (lane == 0) atomicAdd(&g_acc, x);
    }
}

__global__ void finalize_kernel(float* out) {
    out[0] = (float)(g_acc / (double)((long long)NROWS * T_LEN));
}

extern "C" void kernel_launch(void* const* d_in, const int* in_sizes, int n_in,
                              void* d_out, int out_size)
{
    const float* Q   = (const float*)d_in[0];
    const float* eQ  = (const float*)d_in[1];
    const float* tQ  = (const float*)d_in[2];
    const float* r   = (const float*)d_in[3];
    const float* tp  = (const float*)d_in[4];
    const float* bp  = (const float*)d_in[5];
    float* out = (float*)d_out;

    zero_acc_kernel<<<1, 1>>>();
    retrace_kernel<<<NROWS, NTHREADS>>>(Q, eQ, tQ, r, tp, bp);
    finalize_kernel<<<1, 1>>>(out);
}